// round 7
// baseline (speedup 1.0000x reference)
#include <cuda_runtime.h>

#define D_CH 20
#define GV 128
#define NUM_EMB (GV * GV * GV)
#define XCH 8                          // x-chunks (gx/16)
#define NUM_BINS (GV * GV * XCH)       // 131072 : key = ((gz*128+gy)*8) + gx/16
#define CAP 24                         // slots per bin (Poisson(7.6) overflow ~1e-7/bin)
#define SLOTS (NUM_BINS * CAP)         // 3,145,728
#define OVF_MAX (1 << 20)
#define MAXP (1 << 21)

__device__ int    g_cnt[NUM_BINS];
__device__ int    g_ovf_cnt;
__device__ float4 g_sorted[SLOTS];     // ~50 MB static scratch
__device__ float4 g_ovf[OVF_MAX];

__global__ void zero_kernel()
{
    int i = blockIdx.x * blockDim.x + threadIdx.x;
    if (i < NUM_BINS) g_cnt[i] = 0;
    if (i == 0) g_ovf_cnt = 0;
}

// ONE fused pass: bin + rank + scatter into fixed-capacity slots.
__global__ void binscatter_kernel(const float* __restrict__ x, int n)
{
    int p = blockIdx.x * blockDim.x + threadIdx.x;
    if (p >= n) return;
    float px = __ldg(&x[p * 3 + 0]);
    float py = __ldg(&x[p * 3 + 1]);
    float pz = __ldg(&x[p * 3 + 2]);

    int gx = (int)floorf((px + 1.0f) * 0.5f * (float)GV);
    int gy = (int)floorf((py + 1.0f) * 0.5f * (float)GV);
    int gz = (int)floorf((pz + 1.0f) * 0.5f * (float)GV);
    gx = min(max(gx, 0), GV - 1);
    gy = min(max(gy, 0), GV - 1);
    gz = min(max(gz, 0), GV - 1);

    int bin = ((gz * GV + gy) * XCH) + (gx >> 4);
    int rank = atomicAdd(&g_cnt[bin], 1);
    float4 v = make_float4(px, py, pz, __int_as_float(p));
    if (rank < CAP) {
        __stcs(&g_sorted[bin * CAP + rank], v);
    } else {
        int o = atomicAdd(&g_ovf_cnt, 1);
        if (o < OVF_MAX) g_ovf[o] = v;
    }
}

__device__ __forceinline__ void interp_point(
    const float* __restrict__ grid, float* __restrict__ out,
    float px, float py, float pz, int orig, unsigned int c4)
{
    unsigned int cbase = c4 * 4u;

    float tx = (px + 1.0f) * 0.5f * (float)GV;
    float ty = (py + 1.0f) * 0.5f * (float)GV;
    float tz = (pz + 1.0f) * 0.5f * (float)GV;
    int gx = (int)floorf(tx);
    int gy = (int)floorf(ty);
    int gz = (int)floorf(tz);

    const float inv_v2 = 2.0f / (float)GV;   // exact in fp32
    float x1 = (float)gx * inv_v2 - 1.0f;
    float x2 = (float)(gx + 1) * inv_v2 - 1.0f;
    float y1 = (float)gy * inv_v2 - 1.0f;
    float y2 = (float)(gy + 1) * inv_v2 - 1.0f;
    float z1 = (float)gz * inv_v2 - 1.0f;
    float z2 = (float)(gz + 1) * inv_v2 - 1.0f;

    const float inv_den = 64.0f;             // 1/(2/128), exact
    float wx0 = (x2 - px) * inv_den;
    float wx1 = (px - x1) * inv_den;
    float wy0 = (y2 - py) * inv_den;
    float wy1 = (py - y1) * inv_den;
    float wz0 = (z2 - pz) * inv_den;
    float wz1 = (pz - z1) * inv_den;

    int base = gx + gy * GV + gz * GV * GV;
    const int maxi = NUM_EMB - 1;
    int f000 = min(base,                  maxi);
    int f100 = min(base + 1,              maxi);
    int f010 = min(base + GV,             maxi);
    int f110 = min(base + GV + 1,         maxi);
    int f001 = min(base + GV*GV,          maxi);
    int f101 = min(base + GV*GV + 1,      maxi);
    int f011 = min(base + GV*GV + GV,     maxi);
    int f111 = min(base + GV*GV + GV + 1, maxi);

    const float4* g4 = (const float4*)grid;
    float4 q000 = __ldg(&g4[((size_t)f000 * D_CH + cbase) >> 2]);
    float4 q100 = __ldg(&g4[((size_t)f100 * D_CH + cbase) >> 2]);
    float4 q010 = __ldg(&g4[((size_t)f010 * D_CH + cbase) >> 2]);
    float4 q110 = __ldg(&g4[((size_t)f110 * D_CH + cbase) >> 2]);
    float4 q001 = __ldg(&g4[((size_t)f001 * D_CH + cbase) >> 2]);
    float4 q101 = __ldg(&g4[((size_t)f101 * D_CH + cbase) >> 2]);
    float4 q011 = __ldg(&g4[((size_t)f011 * D_CH + cbase) >> 2]);
    float4 q111 = __ldg(&g4[((size_t)f111 * D_CH + cbase) >> 2]);

    float4 r;
    {
        float fx0 = wx0 * q000.x + wx1 * q100.x;
        float fx1 = wx0 * q010.x + wx1 * q110.x;
        float fx2 = wx0 * q001.x + wx1 * q101.x;
        float fx3 = wx0 * q011.x + wx1 * q111.x;
        r.x = wz0 * (wy0 * fx0 + wy1 * fx1) + wz1 * (wy0 * fx2 + wy1 * fx3);
    }
    {
        float fx0 = wx0 * q000.y + wx1 * q100.y;
        float fx1 = wx0 * q010.y + wx1 * q110.y;
        float fx2 = wx0 * q001.y + wx1 * q101.y;
        float fx3 = wx0 * q011.y + wx1 * q111.y;
        r.y = wz0 * (wy0 * fx0 + wy1 * fx1) + wz1 * (wy0 * fx2 + wy1 * fx3);
    }
    {
        float fx0 = wx0 * q000.z + wx1 * q100.z;
        float fx1 = wx0 * q010.z + wx1 * q110.z;
        float fx2 = wx0 * q001.z + wx1 * q101.z;
        float fx3 = wx0 * q011.z + wx1 * q111.z;
        r.z = wz0 * (wy0 * fx0 + wy1 * fx1) + wz1 * (wy0 * fx2 + wy1 * fx3);
    }
    {
        float fx0 = wx0 * q000.w + wx1 * q100.w;
        float fx1 = wx0 * q010.w + wx1 * q110.w;
        float fx2 = wx0 * q001.w + wx1 * q101.w;
        float fx3 = wx0 * q011.w + wx1 * q111.w;
        r.w = wz0 * (wy0 * fx0 + wy1 * fx1) + wz1 * (wy0 * fx2 + wy1 * fx3);
    }

    __stcs((float4*)out + (size_t)orig * 5u + c4, r);
}

// Gather over bin slots in spatial (gz, gy, x-chunk) order.
__global__ void __launch_bounds__(256) gather_kernel(
    const float* __restrict__ grid,
    float* __restrict__ out)
{
    unsigned int gid = blockIdx.x * 256u + threadIdx.x;
    if (gid >= (unsigned int)SLOTS * 5u) return;

    unsigned int slot = gid / 5u;
    unsigned int c4   = gid - slot * 5u;
    unsigned int bin  = slot / CAP;
    unsigned int r    = slot - bin * CAP;

    int cnt = __ldg(&g_cnt[bin]);
    if ((int)r >= cnt) return;           // empty slot

    float4 pt = __ldcs(&g_sorted[slot]);
    interp_point(grid, out, pt.x, pt.y, pt.z, __float_as_int(pt.w), c4);
}

// Handles the (statistically near-empty) overflow list. Grid-stride; each
// thread does all 20 channels of one point.
__global__ void overflow_kernel(const float* __restrict__ grid,
                                float* __restrict__ out)
{
    int n = g_ovf_cnt;
    if (n > OVF_MAX) n = OVF_MAX;
    for (int i = blockIdx.x * blockDim.x + threadIdx.x; i < n;
         i += gridDim.x * blockDim.x) {
        float4 pt = g_ovf[i];
        for (unsigned int c4 = 0; c4 < 5; c4++)
            interp_point(grid, out, pt.x, pt.y, pt.z, __float_as_int(pt.w), c4);
    }
}

// Fallback (unsorted) path if n_pts exceeds static scratch capacity.
__global__ void __launch_bounds__(256) gather_direct_kernel(
    const float* __restrict__ x,
    const float* __restrict__ grid,
    float* __restrict__ out,
    int n_pts)
{
    unsigned int gid = blockIdx.x * 256u + threadIdx.x;
    unsigned int total = (unsigned int)n_pts * 5u;
    if (gid >= total) return;
    unsigned int p = gid / 5u;
    unsigned int c4 = gid - p * 5u;
    float px = __ldg(&x[p * 3 + 0]);
    float py = __ldg(&x[p * 3 + 1]);
    float pz = __ldg(&x[p * 3 + 2]);
    interp_point(grid, out, px, py, pz, (int)p, c4);
}

extern "C" void kernel_launch(void* const* d_in, const int* in_sizes, int n_in,
                              void* d_out, int out_size)
{
    const float* x    = (const float*)d_in[0];
    const float* grid = (const float*)d_in[1];
    float* out        = (float*)d_out;

    int n_pts = in_sizes[0] / 3;

    if (n_pts > MAXP) {
        unsigned int total = (unsigned int)n_pts * 5u;
        gather_direct_kernel<<<(total + 255u) / 256u, 256>>>(x, grid, out, n_pts);
        return;
    }

    int pb = (n_pts + 255) / 256;
    unsigned int gthreads = (unsigned int)SLOTS * 5u;

    zero_kernel<<<(NUM_BINS + 1023) / 1024, 1024>>>();
    binscatter_kernel<<<pb, 256>>>(x, n_pts);
    gather_kernel<<<(gthreads + 255u) / 256u, 256>>>(grid, out);
    overflow_kernel<<<64, 256>>>(grid, out);
}

// round 8
// speedup vs baseline: 1.5488x; 1.5488x over previous
#include <cuda_runtime.h>

#define D_CH 20
#define GV 128
#define NUM_EMB (GV * GV * GV)
#define XCH 8                           // gx / 16
#define NUM_BINS (GV * GV * XCH)        // 131072
#define MAXP (1 << 21)
#define SCAN_BLOCKS 512                 // 512 blocks x 256 = 131072

__device__ int    g_hist[NUM_BINS];
__device__ int    g_base[NUM_BINS];
__device__ int    g_blocksum[SCAN_BLOCKS];
__device__ float4 g_tmp[MAXP];          // (x,y,z, rank-bits)
__device__ float4 g_sorted[MAXP];       // (x,y,z, orig-bits)

__device__ __forceinline__ int bin_of(float px, float py, float pz)
{
    int gx = (int)floorf((px + 1.0f) * 0.5f * (float)GV);
    int gy = (int)floorf((py + 1.0f) * 0.5f * (float)GV);
    int gz = (int)floorf((pz + 1.0f) * 0.5f * (float)GV);
    gx = min(max(gx, 0), GV - 1);
    gy = min(max(gy, 0), GV - 1);
    gz = min(max(gz, 0), GV - 1);
    return ((gz * GV + gy) * XCH) + (gx >> 4);
}

__global__ void zero_kernel()
{
    int i = blockIdx.x * blockDim.x + threadIdx.x;
    if (i < NUM_BINS) g_hist[i] = 0;
}

// Pass 1: count + per-point rank, stash point+rank in temp (stays in L2).
__global__ void hist_rank_kernel(const float* __restrict__ x, int n)
{
    int p = blockIdx.x * blockDim.x + threadIdx.x;
    if (p >= n) return;
    float px = __ldg(&x[p * 3 + 0]);
    float py = __ldg(&x[p * 3 + 1]);
    float pz = __ldg(&x[p * 3 + 2]);
    int bin  = bin_of(px, py, pz);
    int rank = atomicAdd(&g_hist[bin], 1);
    g_tmp[p] = make_float4(px, py, pz, __int_as_float(rank));
}

// Scan stage A: per-block sums of 256 bins.
__global__ void scanA_kernel()
{
    __shared__ int sh[256];
    int i = blockIdx.x * 256 + threadIdx.x;
    int v = g_hist[i];
    sh[threadIdx.x] = v;
    __syncthreads();
    // reduce
    for (int off = 128; off > 0; off >>= 1) {
        if (threadIdx.x < off) sh[threadIdx.x] += sh[threadIdx.x + off];
        __syncthreads();
    }
    if (threadIdx.x == 0) g_blocksum[blockIdx.x] = sh[0];
}

// Scan stage B: exclusive scan of 512 block sums (one block).
__global__ void scanB_kernel()
{
    __shared__ int sh[SCAN_BLOCKS];
    int tid = threadIdx.x;            // 512 threads
    sh[tid] = g_blocksum[tid];
    __syncthreads();
    for (int off = 1; off < SCAN_BLOCKS; off <<= 1) {
        int v = sh[tid];
        int add = (tid >= off) ? sh[tid - off] : 0;
        __syncthreads();
        sh[tid] = v + add;
        __syncthreads();
    }
    g_blocksum[tid] = (tid == 0) ? 0 : sh[tid - 1];   // exclusive
}

// Scan stage C: per-block exclusive scan + block base -> g_base.
__global__ void scanC_kernel()
{
    __shared__ int sh[256];
    int tid = threadIdx.x;
    int i = blockIdx.x * 256 + tid;
    int v = g_hist[i];
    sh[tid] = v;
    __syncthreads();
    // inclusive Hillis-Steele
    for (int off = 1; off < 256; off <<= 1) {
        int a = sh[tid];
        int add = (tid >= off) ? sh[tid - off] : 0;
        __syncthreads();
        sh[tid] = a + add;
        __syncthreads();
    }
    int excl = sh[tid] - v;
    g_base[i] = excl + g_blocksum[blockIdx.x];
}

// Pass 2: atomic-free scatter, pos = base[bin] + rank.
__global__ void scatter_kernel(int n)
{
    int p = blockIdx.x * blockDim.x + threadIdx.x;
    if (p >= n) return;
    float4 t = g_tmp[p];
    int bin  = bin_of(t.x, t.y, t.z);
    int pos  = g_base[bin] + __float_as_int(t.w);
    g_sorted[pos] = make_float4(t.x, t.y, t.z, __int_as_float(p));
}

__device__ __forceinline__ void interp_point(
    const float* __restrict__ grid, float* __restrict__ out,
    float px, float py, float pz, int orig, unsigned int c4)
{
    unsigned int cbase = c4 * 4u;

    int gx = (int)floorf((px + 1.0f) * 0.5f * (float)GV);
    int gy = (int)floorf((py + 1.0f) * 0.5f * (float)GV);
    int gz = (int)floorf((pz + 1.0f) * 0.5f * (float)GV);

    const float inv_v2 = 2.0f / (float)GV;   // exact in fp32
    float x1 = (float)gx * inv_v2 - 1.0f;
    float x2 = (float)(gx + 1) * inv_v2 - 1.0f;
    float y1 = (float)gy * inv_v2 - 1.0f;
    float y2 = (float)(gy + 1) * inv_v2 - 1.0f;
    float z1 = (float)gz * inv_v2 - 1.0f;
    float z2 = (float)(gz + 1) * inv_v2 - 1.0f;

    const float inv_den = 64.0f;             // 1/(2/128), exact
    float wx0 = (x2 - px) * inv_den;
    float wx1 = (px - x1) * inv_den;
    float wy0 = (y2 - py) * inv_den;
    float wy1 = (py - y1) * inv_den;
    float wz0 = (z2 - pz) * inv_den;
    float wz1 = (pz - z1) * inv_den;

    int base = gx + gy * GV + gz * GV * GV;
    const int maxi = NUM_EMB - 1;
    int f000 = min(base,                  maxi);
    int f100 = min(base + 1,              maxi);
    int f010 = min(base + GV,             maxi);
    int f110 = min(base + GV + 1,         maxi);
    int f001 = min(base + GV*GV,          maxi);
    int f101 = min(base + GV*GV + 1,      maxi);
    int f011 = min(base + GV*GV + GV,     maxi);
    int f111 = min(base + GV*GV + GV + 1, maxi);

    const float4* g4 = (const float4*)grid;
    float4 q000 = __ldg(&g4[((size_t)f000 * D_CH + cbase) >> 2]);
    float4 q100 = __ldg(&g4[((size_t)f100 * D_CH + cbase) >> 2]);
    float4 q010 = __ldg(&g4[((size_t)f010 * D_CH + cbase) >> 2]);
    float4 q110 = __ldg(&g4[((size_t)f110 * D_CH + cbase) >> 2]);
    float4 q001 = __ldg(&g4[((size_t)f001 * D_CH + cbase) >> 2]);
    float4 q101 = __ldg(&g4[((size_t)f101 * D_CH + cbase) >> 2]);
    float4 q011 = __ldg(&g4[((size_t)f011 * D_CH + cbase) >> 2]);
    float4 q111 = __ldg(&g4[((size_t)f111 * D_CH + cbase) >> 2]);

    float4 r;
    {
        float fx0 = wx0 * q000.x + wx1 * q100.x;
        float fx1 = wx0 * q010.x + wx1 * q110.x;
        float fx2 = wx0 * q001.x + wx1 * q101.x;
        float fx3 = wx0 * q011.x + wx1 * q111.x;
        r.x = wz0 * (wy0 * fx0 + wy1 * fx1) + wz1 * (wy0 * fx2 + wy1 * fx3);
    }
    {
        float fx0 = wx0 * q000.y + wx1 * q100.y;
        float fx1 = wx0 * q010.y + wx1 * q110.y;
        float fx2 = wx0 * q001.y + wx1 * q101.y;
        float fx3 = wx0 * q011.y + wx1 * q111.y;
        r.y = wz0 * (wy0 * fx0 + wy1 * fx1) + wz1 * (wy0 * fx2 + wy1 * fx3);
    }
    {
        float fx0 = wx0 * q000.z + wx1 * q100.z;
        float fx1 = wx0 * q010.z + wx1 * q110.z;
        float fx2 = wx0 * q001.z + wx1 * q101.z;
        float fx3 = wx0 * q011.z + wx1 * q111.z;
        r.z = wz0 * (wy0 * fx0 + wy1 * fx1) + wz1 * (wy0 * fx2 + wy1 * fx3);
    }
    {
        float fx0 = wx0 * q000.w + wx1 * q100.w;
        float fx1 = wx0 * q010.w + wx1 * q110.w;
        float fx2 = wx0 * q001.w + wx1 * q101.w;
        float fx3 = wx0 * q011.w + wx1 * q111.w;
        r.w = wz0 * (wy0 * fx0 + wy1 * fx1) + wz1 * (wy0 * fx2 + wy1 * fx3);
    }

    __stcs((float4*)out + (size_t)orig * 5u + c4, r);
}

// Gather in sorted (gz, gy, x-chunk) order: 5 threads/point, dense.
__global__ void __launch_bounds__(256) gather_kernel(
    const float* __restrict__ grid,
    float* __restrict__ out,
    int n_pts)
{
    unsigned int gid = blockIdx.x * 256u + threadIdx.x;
    unsigned int total = (unsigned int)n_pts * 5u;
    if (gid >= total) return;

    unsigned int sp = gid / 5u;
    unsigned int c4 = gid - sp * 5u;

    float4 pt = __ldg(&g_sorted[sp]);     // L2-resident (written by scatter)
    interp_point(grid, out, pt.x, pt.y, pt.z, __float_as_int(pt.w), c4);
}

// Fallback (unsorted) path if n_pts exceeds static scratch capacity.
__global__ void __launch_bounds__(256) gather_direct_kernel(
    const float* __restrict__ x,
    const float* __restrict__ grid,
    float* __restrict__ out,
    int n_pts)
{
    unsigned int gid = blockIdx.x * 256u + threadIdx.x;
    unsigned int total = (unsigned int)n_pts * 5u;
    if (gid >= total) return;
    unsigned int p = gid / 5u;
    unsigned int c4 = gid - p * 5u;
    float px = __ldg(&x[p * 3 + 0]);
    float py = __ldg(&x[p * 3 + 1]);
    float pz = __ldg(&x[p * 3 + 2]);
    interp_point(grid, out, px, py, pz, (int)p, c4);
}

extern "C" void kernel_launch(void* const* d_in, const int* in_sizes, int n_in,
                              void* d_out, int out_size)
{
    const float* x    = (const float*)d_in[0];
    const float* grid = (const float*)d_in[1];
    float* out        = (float*)d_out;

    int n_pts = in_sizes[0] / 3;

    if (n_pts > MAXP) {
        unsigned int total = (unsigned int)n_pts * 5u;
        gather_direct_kernel<<<(total + 255u) / 256u, 256>>>(x, grid, out, n_pts);
        return;
    }

    int pb = (n_pts + 255) / 256;
    unsigned int total = (unsigned int)n_pts * 5u;

    zero_kernel<<<(NUM_BINS + 1023) / 1024, 1024>>>();
    hist_rank_kernel<<<pb, 256>>>(x, n_pts);
    scanA_kernel<<<SCAN_BLOCKS, 256>>>();
    scanB_kernel<<<1, SCAN_BLOCKS>>>();
    scanC_kernel<<<SCAN_BLOCKS, 256>>>();
    scatter_kernel<<<pb, 256>>>(n_pts);
    gather_kernel<<<(total + 255u) / 256u, 256>>>(grid, out, n_pts);
}